// round 17
// baseline (speedup 1.0000x reference)
#include <cuda_runtime.h>
#include <cuda_fp16.h>
#include <cstdint>

#define TT 256
#define BB 512
#define FF 64
#define UU 128
#define NG 512           // 4*U
#define TB (TT*BB)       // 131072

// ---------- static device scratch (no allocation) ----------
__device__ __half g_xz1[(size_t)TB * NG];   // layer-1 xz fp16, gate-interleaved [m][u*4+g]
__device__ __half g_xz2[(size_t)TB * NG];   // layer-2 xz fp16 (written by fused rnn0)
__device__ float  g_hlast[BB * UU];         // layer-2 final h

// ---------- helpers ----------
__device__ __forceinline__ void mma16816(float* d, const uint32_t* a, uint32_t b0, uint32_t b1) {
    asm volatile(
        "mma.sync.aligned.m16n8k16.row.col.f32.f16.f16.f32 "
        "{%0,%1,%2,%3}, {%4,%5,%6,%7}, {%8,%9}, {%0,%1,%2,%3};"
        : "+f"(d[0]), "+f"(d[1]), "+f"(d[2]), "+f"(d[3])
        : "r"(a[0]), "r"(a[1]), "r"(a[2]), "r"(a[3]), "r"(b0), "r"(b1));
}
__device__ __forceinline__ void ldsm4(uint32_t* a, const __half* p) {
    uint32_t addr = (uint32_t)__cvta_generic_to_shared(p);
    asm volatile("ldmatrix.sync.aligned.m8n8.x4.shared.b16 {%0,%1,%2,%3}, [%4];"
                 : "=r"(a[0]), "=r"(a[1]), "=r"(a[2]), "=r"(a[3]) : "r"(addr));
}
__device__ __forceinline__ float tanha(float x) {
    float r;
    asm("tanh.approx.f32 %0, %1;" : "=f"(r) : "f"(x));
    return r;
}
__device__ __forceinline__ float sigm(float x) {
    return fmaf(0.5f, tanha(0.5f * x), 0.5f);
}

// ---------- GEMM: out16[M][perm(512)] = A(x fp32) @ W1 + b1, K=64 ----------
// Gate-interleave permutation applied at Wp/bias gather; coalesced half2 stores.
// Software-pipelined, double-buffered As, ONE barrier/tile.
__global__ void __launch_bounds__(256, 2)
k_gemm64(const float* __restrict__ X, const float* __restrict__ Wg,
         const float* __restrict__ bias, __half* __restrict__ out, int Mtiles) {
    extern __shared__ char sm[];
    const int K = 64, LDW = 136, ldA = K + 8;
    uint32_t* Wp = (uint32_t*)sm;                                  // [32][136] half2
    __half*   As = (__half*)(sm + 32 * LDW * 4);                   // [2][64][72]
    const int ABUF = 64 * ldA;
    int tid = threadIdx.x, w = tid >> 5, lane = tid & 31;
    int n0 = (blockIdx.x & 3) * 128;
    int tile0 = blockIdx.x >> 2, tstep = gridDim.x >> 2;

    for (int i = tid; i < 32 * 128; i += 256) {
        int kk = i >> 7, nl = i & 127;
        int P = n0 + nl;
        int l = (P & 3) * 128 + (P >> 2);
        __half2 h2 = __floats2half2_rn(Wg[(size_t)(2 * kk) * NG + l],
                                       Wg[(size_t)(2 * kk + 1) * NG + l]);
        Wp[kk * LDW + nl] = *(uint32_t*)&h2;
    }

    float4 stg[4];
    auto ldtile = [&](int m0) {
#pragma unroll
        for (int s = 0; s < 4; s++) {
            int i = tid + 256 * s;
            int r = i >> 4, c = (i & 15) * 4;
            int m = m0 + r, t = m >> 9, b = m & 511;
            stg[s] = *(const float4*)&X[((size_t)(b << 8 | t)) * FF + c];
        }
    };
    auto sttile = [&](int buf) {
#pragma unroll
        for (int s = 0; s < 4; s++) {
            int i = tid + 256 * s;
            int r = i >> 4, c = (i & 15) * 4;
            *(__half2*)&As[buf * ABUF + r * ldA + c]     = __floats2half2_rn(stg[s].x, stg[s].y);
            *(__half2*)&As[buf * ABUF + r * ldA + c + 2] = __floats2half2_rn(stg[s].z, stg[s].w);
        }
    };

    int cur = 0;
    ldtile(tile0 * 64);
    sttile(0);
    __syncthreads();

    for (int tile = tile0; tile < Mtiles; tile += tstep) {
        int m0 = tile * 64;
        bool havenext = (tile + tstep < Mtiles);
        if (havenext) ldtile((tile + tstep) * 64);

        float acc[4][2][4];
#pragma unroll
        for (int mt = 0; mt < 4; mt++)
#pragma unroll
            for (int nt = 0; nt < 2; nt++)
#pragma unroll
                for (int q = 0; q < 4; q++) acc[mt][nt][q] = 0.f;

        const __half* Ac = As + cur * ABUF;
#pragma unroll
        for (int kt = 0; kt < 4; kt++) {
            uint32_t a[4][4];
#pragma unroll
            for (int mt = 0; mt < 4; mt++) {
                int row = mt * 16 + (lane & 15);
                int col = kt * 16 + (lane >> 4) * 8;
                ldsm4(a[mt], &Ac[row * ldA + col]);
            }
            int c4 = lane & 3;
#pragma unroll
            for (int nt = 0; nt < 2; nt++) {
                int nl = w * 16 + nt * 8 + (lane >> 2);
                uint32_t b0 = Wp[(kt * 8 + c4) * LDW + nl];
                uint32_t b1 = Wp[(kt * 8 + 4 + c4) * LDW + nl];
#pragma unroll
                for (int mt = 0; mt < 4; mt++) mma16816(acc[mt][nt], a[mt], b0, b1);
            }
        }

#pragma unroll
        for (int mt = 0; mt < 4; mt++) {
            int r0 = m0 + mt * 16 + (lane >> 2);
#pragma unroll
            for (int nt = 0; nt < 2; nt++) {
                int cc = n0 + w * 16 + nt * 8 + (lane & 3) * 2;
                int l0 = (cc & 3) * 128 + (cc >> 2);
                int l1 = ((cc + 1) & 3) * 128 + ((cc + 1) >> 2);
                float bb0 = __ldg(&bias[l0]), bb1 = __ldg(&bias[l1]);
                *(__half2*)&out[(size_t)r0 * NG + cc] =
                    __floats2half2_rn(acc[mt][nt][0] + bb0, acc[mt][nt][1] + bb1);
                *(__half2*)&out[(size_t)(r0 + 8) * NG + cc] =
                    __floats2half2_rn(acc[mt][nt][2] + bb0, acc[mt][nt][3] + bb1);
            }
        }

        if (havenext) sttile(cur ^ 1);
        __syncthreads();
        cur ^= 1;
    }
}

// ---------- LSTM recurrence ----------
// 128 CTAs x 4 batches, 512 threads. Warp w: units [w*8,w*8+8), 2 m16 gate-pair
// tiles. LAYER 0 (FUSED): also computes xz2 = h @ W2 + b2 inline — W2^T frags
// ldsm'd per step from the As smem (restaged after ua preload), sharing the
// same h B-fragments; result stored gate-interleaved to xzout. No g_hs at all.
// n>=4 B-frags are zero -> lanes 16-31 skip hp LDS. ONE barrier per step.
template <int LAYER>
__global__ void __launch_bounds__(512, 1)
k_rnn(const float* __restrict__ Urec, const float* __restrict__ W2g,
      const float* __restrict__ b2, const __half* __restrict__ xzin,
      __half* __restrict__ xzout) {
    extern __shared__ char sm[];
    __half* As = (__half*)sm;                        // [512][136] = 139264 B
    char*   hp = sm + 512 * 136 * 2;                 // 2 phases x 2048 B
    const int th = threadIdx.x, w = th >> 5, lane = th & 31;
    const int b0 = blockIdx.x * 4;

    // stage permuted U^T: row = w*32 + mt*16 + sub*8 + r -> G = (2mt+sub)*128 + w*8 + r
    for (int i = th; i < 512 * 128; i += 512) {
        int row = i >> 7, k = i & 127;
        int ww = row >> 5, mt = (row >> 4) & 1, sub = (row >> 3) & 1, r = row & 7;
        int G = (2 * mt + sub) * 128 + ww * 8 + r;
        As[row * 136 + k] = __float2half(Urec[(size_t)k * NG + G]);
    }
    for (int i = th; i < 1024; i += 512) ((uint32_t*)hp)[i] = 0u;
    __syncthreads();

    uint32_t ua[2][8][4];
#pragma unroll
    for (int mt = 0; mt < 2; mt++) {
        int row = w * 32 + mt * 16 + (lane & 15);
#pragma unroll
        for (int kt = 0; kt < 8; kt++)
            ldsm4(ua[mt][kt], &As[row * 136 + kt * 16 + (lane >> 4) * 8]);
    }
    __syncthreads();

    if (LAYER == 0) {
        // restage As with permuted W2^T (same row mapping); ua already in regs
        for (int i = th; i < 512 * 128; i += 512) {
            int row = i >> 7, k = i & 127;
            int ww = row >> 5, mt = (row >> 4) & 1, sub = (row >> 3) & 1, r = row & 7;
            int G = (2 * mt + sub) * 128 + ww * 8 + r;
            As[row * 136 + k] = __float2half(W2g[(size_t)k * NG + G]);
        }
        __syncthreads();
    }

    const int q  = lane & 3, r8 = lane >> 2;
    const int ut = w * 8 + r8;                      // this lane's unit
    const int srcl = (lane & 28) | (q >> 1);        // shfl source lane
    const int hoff = (ut >> 4) * 256 + ((ut & 7) >> 1) * 64 + q * 8
                   + ((ut >> 3) & 1) * 4 + (ut & 1) * 2;
    const bool bload = (lane < 16);                 // n>=4 fragments are zero

    float b2r[4];
    if (LAYER == 0) {
#pragma unroll
        for (int g = 0; g < 4; g++) b2r[g] = __ldg(&b2[g * 128 + ut]);
    }

    uint2 xc = *(const uint2*)&xzin[((size_t)(b0 + q)) * NG + ut * 4];
    float cst = 0.f;
    int ph = 0;

    const int TEND = (LAYER == 0) ? TT + 1 : TT;
    for (int t = 0; t < TEND; t++) {
        // ---- mma: U-acc (single chain) + W2-acc (LAYER 0), shared B-frags ----
        float acc[2][4], z2[2][4];
#pragma unroll
        for (int mt = 0; mt < 2; mt++)
#pragma unroll
            for (int j = 0; j < 4; j++) { acc[mt][j] = 0.f; z2[mt][j] = 0.f; }
        const char* hpc = hp + ph * 2048;
#pragma unroll
        for (int kt = 0; kt < 8; kt++) {
            uint2 bf = make_uint2(0u, 0u);
            if (bload)
                bf = *(const uint2*)(hpc + kt * 256 + (lane & 3) * 64 + (lane >> 2) * 8);
            mma16816(acc[0], ua[0][kt], bf.x, bf.y);
            mma16816(acc[1], ua[1][kt], bf.x, bf.y);
            if (LAYER == 0) {
                uint32_t wa[4], wb[4];
                ldsm4(wa, &As[(w * 32 + (lane & 15)) * 136 + kt * 16 + (lane >> 4) * 8]);
                ldsm4(wb, &As[(w * 32 + 16 + (lane & 15)) * 136 + kt * 16 + (lane >> 4) * 8]);
                mma16816(z2[0], wa, bf.x, bf.y);
                mma16816(z2[1], wb, bf.x, bf.y);
            }
        }

        // prefetch next step's xz
        uint2 xn = xc;
        if (t + 1 < TT)
            xn = *(const uint2*)&xzin[((size_t)(t + 1) * BB + b0 + q) * NG + ut * 4];

        // ---- z2 extraction + store (row t-1), LAYER 0 only ----
        if (LAYER == 0 && t > 0) {
            float va, vb, zi, zf, zg, zo;
            va = __shfl_sync(0xffffffffu, z2[0][0], srcl);
            vb = __shfl_sync(0xffffffffu, z2[0][1], srcl);
            zi = ((q & 1) ? vb : va) + b2r[0];
            va = __shfl_sync(0xffffffffu, z2[0][2], srcl);
            vb = __shfl_sync(0xffffffffu, z2[0][3], srcl);
            zf = ((q & 1) ? vb : va) + b2r[1];
            va = __shfl_sync(0xffffffffu, z2[1][0], srcl);
            vb = __shfl_sync(0xffffffffu, z2[1][1], srcl);
            zg = ((q & 1) ? vb : va) + b2r[2];
            va = __shfl_sync(0xffffffffu, z2[1][2], srcl);
            vb = __shfl_sync(0xffffffffu, z2[1][3], srcl);
            zo = ((q & 1) ? vb : va) + b2r[3];
            __half2 lo = __floats2half2_rn(zi, zf);
            __half2 hi = __floats2half2_rn(zg, zo);
            uint2 pk;
            pk.x = *(uint32_t*)&lo;
            pk.y = *(uint32_t*)&hi;
            *(uint2*)&xzout[((size_t)(t - 1) * BB + b0 + q) * NG + ut * 4] = pk;
        }

        if (t < TT) {
            // ---- U-gate extraction: 8 shfl + 4 selects ----
            float va, vb, iz, fz, gz, oz;
            va = __shfl_sync(0xffffffffu, acc[0][0], srcl);
            vb = __shfl_sync(0xffffffffu, acc[0][1], srcl);
            iz = (q & 1) ? vb : va;
            va = __shfl_sync(0xffffffffu, acc[0][2], srcl);
            vb = __shfl_sync(0xffffffffu, acc[0][3], srcl);
            fz = (q & 1) ? vb : va;
            va = __shfl_sync(0xffffffffu, acc[1][0], srcl);
            vb = __shfl_sync(0xffffffffu, acc[1][1], srcl);
            gz = (q & 1) ? vb : va;
            va = __shfl_sync(0xffffffffu, acc[1][2], srcl);
            vb = __shfl_sync(0xffffffffu, acc[1][3], srcl);
            oz = (q & 1) ? vb : va;

            // ---- elementwise: ONE cell per lane ----
            float2 flo = __half22float2(*(__half2*)&xc.x);   // (i, f)
            float2 fhi = __half22float2(*(__half2*)&xc.y);   // (g, o)
            float iv = sigm(iz + flo.x);
            float fv = sigm(fz + flo.y);
            float gv = tanha(gz + fhi.x);
            float ov = sigm(oz + fhi.y);
            cst = fv * cst + iv * gv;
            float hv = ov * tanha(cst);
            __half hh = __float2half(hv);
            // LAYER 0 needs h(TT-1) in hp for the final z2 step; LAYER 1 doesn't.
            if ((LAYER == 0 && t < TT) || (LAYER == 1 && t + 1 < TT))
                *(__half*)(hp + (ph ^ 1) * 2048 + hoff) = hh;
            if (LAYER == 1 && t == TT - 1)
                g_hlast[(size_t)(b0 + q) * UU + ut] = hv;
            xc = xn;
        }
        __syncthreads();   // hp[ph^1] complete for next step
        ph ^= 1;
    }
}

// ---------- dense ----------
__global__ void k_dense(const float* __restrict__ Wd, const float* __restrict__ bd,
                        float* __restrict__ out) {
    int b = blockIdx.x * blockDim.x + threadIdx.x;
    if (b >= BB) return;
    float acc = bd[0];
    const float* h = &g_hlast[(size_t)b * UU];
#pragma unroll 8
    for (int u = 0; u < UU; u++) acc = fmaf(h[u], Wd[u], acc);
    out[b] = fmaxf(acc, 0.f);
}

// ---------- launch ----------
extern "C" void kernel_launch(void* const* d_in, const int* in_sizes, int n_in,
                              void* d_out, int out_size) {
    const float* x  = (const float*)d_in[0];
    const float* W1 = (const float*)d_in[1];
    const float* U1 = (const float*)d_in[2];
    const float* b1 = (const float*)d_in[3];
    const float* W2 = (const float*)d_in[4];
    const float* U2 = (const float*)d_in[5];
    const float* b2 = (const float*)d_in[6];
    const float* Wd = (const float*)d_in[7];
    const float* bd = (const float*)d_in[8];
    float* out = (float*)d_out;

    const int SM_G64 = 32 * 136 * 4 + 2 * 64 * 72 * 2;      // 35840
    const int SM_RNN = 512 * 136 * 2 + 2 * 2048;            // 143360

    cudaFuncSetAttribute((const void*)k_gemm64,
                         cudaFuncAttributeMaxDynamicSharedMemorySize, SM_G64);
    cudaFuncSetAttribute((const void*)k_rnn<0>,
                         cudaFuncAttributeMaxDynamicSharedMemorySize, SM_RNN);
    cudaFuncSetAttribute((const void*)k_rnn<1>,
                         cudaFuncAttributeMaxDynamicSharedMemorySize, SM_RNN);

    __half* xz1p;  cudaGetSymbolAddress((void**)&xz1p, g_xz1);
    __half* xz2p;  cudaGetSymbolAddress((void**)&xz2p, g_xz2);

    k_gemm64<<<296, 256, SM_G64>>>(x, W1, b1, xz1p, TB / 64);
    k_rnn<0><<<128, 512, SM_RNN>>>(U1, W2, b2, xz1p, xz2p);
    k_rnn<1><<<128, 512, SM_RNN>>>(U2, nullptr, nullptr, xz2p, nullptr);
    k_dense<<<4, 128>>>(Wd, bd, out);
}